// round 10
// baseline (speedup 1.0000x reference)
#include <cuda_runtime.h>
#include <cuda_fp16.h>
#include <cstdint>
#include <cstddef>
#include <math.h>

#define BNUM 16
#define HW   1024
#define C    512
#define G    32
#define CG   16
#define NQKV 1536
#define MTOT (BNUM * HW)
#define SCALE 0.044194173824159216f   // 512^-0.5
#define NPERS 304                     // persistent CTAs (152 SMs x 2)

// fp16 scratch
__device__ __half g_xh[MTOT * C];
__device__ __half g_qh[MTOT * C];
__device__ __half g_kh[MTOT * C];
__device__ __half g_vh[MTOT * C];
__device__ __half g_sh[(size_t)BNUM * HW * HW];
__device__ __half g_oh[MTOT * C];
__device__ __half g_wqkvh[NQKV * C];   // permuted: [n'=e*512+ch][k], q-scale folded
__device__ __half g_wouth[C * C];
__device__ float  g_bqr[NQKV];         // permuted (scaled) qkv bias

// ---------------------------------------------------------------------------
// helpers
// ---------------------------------------------------------------------------
__device__ __forceinline__ uint32_t smaddr(const void* p) {
    return (uint32_t)__cvta_generic_to_shared(p);
}
__device__ __forceinline__ uint32_t swz(uint32_t off) {       // SW128 for 128B rows
    return off ^ ((off >> 3) & 0x70);
}
__device__ __forceinline__ void ldsm4(uint32_t a, uint32_t& r0, uint32_t& r1,
                                      uint32_t& r2, uint32_t& r3) {
    asm volatile("ldmatrix.sync.aligned.m8n8.x4.shared.b16 {%0,%1,%2,%3},[%4];"
                 : "=r"(r0), "=r"(r1), "=r"(r2), "=r"(r3) : "r"(a));
}
__device__ __forceinline__ void ldsm4t(uint32_t a, uint32_t& r0, uint32_t& r1,
                                       uint32_t& r2, uint32_t& r3) {
    asm volatile("ldmatrix.sync.aligned.m8n8.x4.trans.shared.b16 {%0,%1,%2,%3},[%4];"
                 : "=r"(r0), "=r"(r1), "=r"(r2), "=r"(r3) : "r"(a));
}
__device__ __forceinline__ void mma16816(float* d, const uint32_t* a, const uint32_t* b) {
    asm volatile(
        "mma.sync.aligned.m16n8k16.row.col.f32.f16.f16.f32 "
        "{%0,%1,%2,%3},{%4,%5,%6,%7},{%8,%9},{%0,%1,%2,%3};"
        : "+f"(d[0]), "+f"(d[1]), "+f"(d[2]), "+f"(d[3])
        : "r"(a[0]), "r"(a[1]), "r"(a[2]), "r"(a[3]), "r"(b[0]), "r"(b[1]));
}
#define CPA16(dst, src) \
    asm volatile("cp.async.cg.shared.global [%0],[%1],16;" ::"r"(dst), "l"(src))
#define CPCOMMIT() asm volatile("cp.async.commit_group;")
#define CPWAIT0()  asm volatile("cp.async.wait_group 0;")
#define CPWAIT1()  asm volatile("cp.async.wait_group 1;")

// ---------------------------------------------------------------------------
// weight converters (QKV permuted to [n'][k] + scale/bias folded)
// ---------------------------------------------------------------------------
__global__ void conv_wqkv(const float* __restrict__ W, const float* __restrict__ bq) {
    int idx = blockIdx.x * 256 + threadIdx.x;
    if (idx >= NQKV * C) return;
    int np = idx >> 9;          // n' = e*512 + ch
    int k  = idx & 511;
    int e  = np >> 9;
    int ch = np & 511;
    float s = (e == 0) ? SCALE : 1.0f;
    g_wqkvh[idx] = __float2half_rn(W[(size_t)k * NQKV + ch * 3 + e] * s);
    if (k == 0) g_bqr[np] = bq[ch * 3 + e] * s;
}
__global__ void f2h_wout(const float* __restrict__ s) {
    int i = blockIdx.x * 256 + threadIdx.x;
    if (i < C * C) g_wouth[i] = __float2half_rn(s[i]);
}

// ---------------------------------------------------------------------------
// GroupNorm -> fp16 g_xh (shuffle reduction, float2/half2)
// ---------------------------------------------------------------------------
__global__ void groupnorm_kernel(const float* __restrict__ in,
                                 const float* __restrict__ gamma,
                                 const float* __restrict__ beta) {
    int b = blockIdx.x >> 5;
    int g = blockIdx.x & 31;
    int tid = threadIdx.x, lane = tid & 31, warp = tid >> 5;
    const float* base = in + (size_t)b * HW * C + g * CG;
    float s = 0.f, ss = 0.f;
    for (int e = tid; e < HW * 8; e += 256) {       // float2 granules
        int pos = e >> 3, c2 = e & 7;
        float2 v = *(const float2*)(base + (size_t)pos * C + c2 * 2);
        s += v.x + v.y; ss += v.x * v.x + v.y * v.y;
    }
#pragma unroll
    for (int o = 16; o; o >>= 1) {
        s  += __shfl_xor_sync(0xffffffffu, s, o);
        ss += __shfl_xor_sync(0xffffffffu, ss, o);
    }
    __shared__ float sm_s[8], sm_ss[8];
    if (lane == 0) { sm_s[warp] = s; sm_ss[warp] = ss; }
    __syncthreads();
    float ts = 0.f, tss = 0.f;
#pragma unroll
    for (int i = 0; i < 8; i++) { ts += sm_s[i]; tss += sm_ss[i]; }
    const float invN = 1.0f / (HW * CG);
    float mean = ts * invN;
    float var  = tss * invN - mean * mean;
    float rstd = rsqrtf(var + 1e-3f);
    __half* outb = g_xh + (size_t)b * HW * C + g * CG;
    for (int e = tid; e < HW * 8; e += 256) {
        int pos = e >> 3, c2 = e & 7;
        float2 v = *(const float2*)(base + (size_t)pos * C + c2 * 2);
        float g0 = gamma[g * CG + c2 * 2], g1 = gamma[g * CG + c2 * 2 + 1];
        float b0 = beta[g * CG + c2 * 2],  b1 = beta[g * CG + c2 * 2 + 1];
        *(__half2*)(outb + (size_t)pos * C + c2 * 2) =
            __floats2half2_rn((v.x - mean) * rstd * g0 + b0,
                              (v.y - mean) * rstd * g1 + b1);
    }
}

// ---------------------------------------------------------------------------
// Persistent fp16 mma.sync GEMM: 128 thr (2x2 warps, 64x64 warp tile),
// block tile 128x128, BK=64, 3-stage cp.async (distance 2), 1 barrier/step,
// frag ping-pong, SW128 swizzle, stage loop unrolled x3 (compile-time stage),
// hoisted ldsm/cp.async addressing, NPERS persistent CTAs, 2 CTAs/SM.
// ---------------------------------------------------------------------------
template <int EPI>
__global__ void __launch_bounds__(128, 2)
gemm_mma(const float* __restrict__ bias,
         const float* __restrict__ resid,
         float* __restrict__ outF) {
    constexpr bool NT  = (EPI <= 1);
    constexpr int  K   = (EPI == 2) ? 1024 : 512;
    constexpr int  KT  = K / 64;
    constexpr int  LDA = (EPI == 2) ? 1024 : 512;
    constexpr int  LDB = 512;
    constexpr int  TX  = (EPI == 0) ? 12 : ((EPI == 1) ? 8 : 4);
    constexpr int  TY  = (EPI == 1 || EPI == 2) ? 8 : 128;
    constexpr int  TZ  = (EPI == 1 || EPI == 2) ? 16 : 1;
    constexpr int  T   = TX * TY * TZ;

    constexpr int ASTG_B = 128 * 128;
    constexpr int BSTG_B = NT ? (128 * 128) : (64 * 136 * 2);
    extern __shared__ char smc[];
    uint32_t sA = smaddr(smc);
    uint32_t sB = sA + 3 * ASTG_B;

    int tid = threadIdx.x, lane = tid & 31, warp = tid >> 5;
    int wm = warp & 1, wn = warp >> 1;
    int bid = blockIdx.x;
    int GP = gridDim.x;
    int myN = (bid < T) ? ((T - 1 - bid) / GP + 1) : 0;
    int S = myN * KT;

    float acc[4][8][4] = {};

    // --- hoisted per-thread cp.async smem offsets (swizzled, stage-relative) ---
    uint32_t cpA[8], cpB[8];
    int64_t  gA[8], gB[8];   // global element offsets (row*ld + chunk*8), tile-relative
    {
        int c0 = tid;
#pragma unroll
        for (int q = 0; q < 8; q++) {
            int c = c0 + q * 128;
            int rA = c >> 3, chA = c & 7;
            cpA[q] = swz((uint32_t)(rA * 128 + chA * 16));
            gA[q]  = (int64_t)rA * LDA + chA * 8;
            if constexpr (NT) {
                cpB[q] = cpA[q];
                gB[q]  = (int64_t)rA * LDB + chA * 8;
            } else {
                int rB = c >> 4, chB = c & 15;
                cpB[q] = (uint32_t)(rB * 272 + chB * 16);
                gB[q]  = (int64_t)rB * LDB + chB * 8;
            }
        }
    }
    // --- hoisted per-warp ldsm offsets ---
    uint32_t aOff[4], bOff[4], bCol[4];
    uint32_t cSel = (uint32_t)((lane >> 4) << 4);   // byte offset 0/16
    uint32_t bRow = (uint32_t)((lane & 15) * 272);  // NN path row term
#pragma unroll
    for (int i = 0; i < 4; i++) {
        uint32_t ra = (uint32_t)((wm * 64 + i * 16 + (lane & 15)) * 128);
        aOff[i] = ra ^ ((ra >> 3) & 0x70);
        if constexpr (NT) {
            uint32_t rb = (uint32_t)((wn * 64 + i * 16 + (lane & 15)) * 128);
            bOff[i] = rb ^ ((rb >> 3) & 0x70);
        } else {
            bCol[i] = (uint32_t)((wn * 64 + i * 16 + ((lane >> 4) << 3)) * 2);
        }
    }

    auto tileinfo = [&](int i, int& m0, int& n0, int& z) {
        int t = bid + i * GP;
        int x = t % TX;
        int y = (t / TX) % TY;
        z = t / (TX * TY);
        m0 = y * 128; n0 = x * 128;
    };

    auto srcptrs = [&](int z, const __half*& A, const __half*& B) {
        if constexpr (EPI == 0)      { A = g_xh;                        B = g_wqkvh; }
        else if constexpr (EPI == 1) { A = g_qh + (size_t)z * HW * C;   B = g_kh + (size_t)z * HW * C; }
        else if constexpr (EPI == 2) { A = g_sh + (size_t)z * HW * HW;  B = g_vh + (size_t)z * HW * C; }
        else                         { A = g_oh;                        B = g_wouth; }
    };

    auto load = [&](int s, uint32_t Asm, uint32_t Bsm) {
        int i = s / KT;
        if (i < myN) {
            int m0, n0, z;
            tileinfo(i, m0, n0, z);
            int k0 = (s % KT) * 64;
            const __half* A;
            const __half* B;
            srcptrs(z, A, B);
            const __half* Ab = A + (size_t)m0 * LDA + k0;
            const __half* Bb = NT ? (B + (size_t)n0 * LDB + k0)
                                  : (B + (size_t)k0 * LDB + n0);
#pragma unroll
            for (int q = 0; q < 8; q++) CPA16(Asm + cpA[q], Ab + gA[q]);
#pragma unroll
            for (int q = 0; q < 8; q++) CPA16(Bsm + cpB[q], Bb + gB[q]);
        }
        CPCOMMIT();
    };

    auto ldfrag = [&](uint32_t Asm, uint32_t Bsm, int ks,
                      uint32_t a[4][4], uint32_t b[8][2]) {
        uint32_t c = cSel + (uint32_t)(2 * ks);
#pragma unroll
        for (int mt = 0; mt < 4; mt++)
            ldsm4(Asm + (aOff[mt] ^ c), a[mt][0], a[mt][1], a[mt][2], a[mt][3]);
        if constexpr (NT) {
#pragma unroll
            for (int ng = 0; ng < 4; ng++) {
                uint32_t r0, r1, r2, r3;
                ldsm4(Bsm + (bOff[ng] ^ c), r0, r1, r2, r3);
                b[2 * ng][0] = r0; b[2 * ng][1] = r2;
                b[2 * ng + 1][0] = r1; b[2 * ng + 1][1] = r3;
            }
        } else {
            uint32_t rterm = bRow + (uint32_t)(ks * 272);
#pragma unroll
            for (int ng = 0; ng < 4; ng++) {
                uint32_t r0, r1, r2, r3;
                ldsm4t(Bsm + rterm + bCol[ng], r0, r1, r2, r3);
                b[2 * ng][0] = r0; b[2 * ng][1] = r1;
                b[2 * ng + 1][0] = r2; b[2 * ng + 1][1] = r3;
            }
        }
    };

    auto mma_all = [&](uint32_t a[4][4], uint32_t b[8][2]) {
#pragma unroll
        for (int mt = 0; mt < 4; mt++)
#pragma unroll
            for (int nt = 0; nt < 8; nt++) mma16816(acc[mt][nt], a[mt], b[nt]);
    };

    auto epilogue = [&](int tile) {
        int m0, n0, z;
        tileinfo(tile, m0, n0, z);
#pragma unroll
        for (int mt = 0; mt < 4; mt++) {
#pragma unroll
            for (int nt = 0; nt < 8; nt++) {
                int r  = m0 + wm * 64 + mt * 16 + (lane >> 2);
                int nl = wn * 64 + nt * 8 + (lane & 3) * 2;
                float* v = acc[mt][nt];
                if constexpr (EPI == 0) {
                    int e = n0 >> 9;
                    __half* dst = (e == 0) ? g_qh : ((e == 1) ? g_kh : g_vh);
                    int ch = (n0 & 511) + nl;
                    float b0f = g_bqr[n0 + nl], b1f = g_bqr[n0 + nl + 1];
                    *(__half2*)&dst[(size_t)r * C + ch] =
                        __floats2half2_rn(v[0] + b0f, v[1] + b1f);
                    *(__half2*)&dst[(size_t)(r + 8) * C + ch] =
                        __floats2half2_rn(v[2] + b0f, v[3] + b1f);
                } else if constexpr (EPI == 1) {
                    size_t base = (size_t)z * HW * HW;
                    int cc = n0 + nl;
                    *(__half2*)&g_sh[base + (size_t)r * HW + cc] =
                        __floats2half2_rn(v[0], v[1]);
                    *(__half2*)&g_sh[base + (size_t)(r + 8) * HW + cc] =
                        __floats2half2_rn(v[2], v[3]);
                } else if constexpr (EPI == 2) {
                    size_t base = (size_t)z * HW * C;
                    int cc = n0 + nl;
                    *(__half2*)&g_oh[base + (size_t)r * C + cc] =
                        __floats2half2_rn(v[0], v[1]);
                    *(__half2*)&g_oh[base + (size_t)(r + 8) * C + cc] =
                        __floats2half2_rn(v[2], v[3]);
                } else {
                    int cc = n0 + nl;
                    outF[(size_t)r * C + cc]     = v[0] + bias[cc]     + resid[(size_t)r * C + cc];
                    outF[(size_t)r * C + cc + 1] = v[1] + bias[cc + 1] + resid[(size_t)r * C + cc + 1];
                    outF[(size_t)(r + 8) * C + cc]     = v[2] + bias[cc]     + resid[(size_t)(r + 8) * C + cc];
                    outF[(size_t)(r + 8) * C + cc + 1] = v[3] + bias[cc + 1] + resid[(size_t)(r + 8) * C + cc + 1];
                }
            }
        }
#pragma unroll
        for (int mt = 0; mt < 4; mt++)
#pragma unroll
            for (int nt = 0; nt < 8; nt++)
#pragma unroll
                for (int j = 0; j < 4; j++) acc[mt][nt][j] = 0.f;
    };

    load(0, sA, sB);
    load(1, sA + ASTG_B, sB + BSTG_B);

    // stage loop unrolled x3: stage index compile-time per copy
    for (int sb = 0; sb < S; sb += 3) {
#pragma unroll
        for (int u = 0; u < 3; u++) {
            int s = sb + u;
            if (s >= S) continue;
            if (s + 1 < S) { CPWAIT1(); } else { CPWAIT0(); }
            __syncthreads();
            constexpr int uu[3] = {2, 0, 1};        // (u+2)%3
            load(s + 2, sA + uu[u] * ASTG_B, sB + uu[u] * BSTG_B);
            uint32_t Asm = sA + u * ASTG_B, Bsm = sB + u * BSTG_B;
            uint32_t a0[4][4], b0[8][2], a1[4][4], b1[8][2];
            ldfrag(Asm, Bsm, 0,  a0, b0);
            ldfrag(Asm, Bsm, 16, a1, b1);
            mma_all(a0, b0);
            ldfrag(Asm, Bsm, 32, a0, b0);
            mma_all(a1, b1);
            ldfrag(Asm, Bsm, 48, a1, b1);
            mma_all(a0, b0);
            mma_all(a1, b1);
            if ((s + 1) % KT == 0) epilogue(s / KT);
        }
    }
}

// ---------------------------------------------------------------------------
// fp16 in-place row softmax over 1024 cols: 128 thr, uint4/thread, 2 barriers
// ---------------------------------------------------------------------------
__global__ void softmax_h() {
    size_t row = blockIdx.x;
    uint4* p = (uint4*)(g_sh + row * HW);
    int tid = threadIdx.x, lane = tid & 31, warp = tid >> 5;
    uint4 raw = p[tid];
    __half2 h[4] = {*(__half2*)&raw.x, *(__half2*)&raw.y,
                    *(__half2*)&raw.z, *(__half2*)&raw.w};
    float2 f[4];
#pragma unroll
    for (int i = 0; i < 4; i++) f[i] = __half22float2(h[i]);

    float m = -1e30f;
#pragma unroll
    for (int i = 0; i < 4; i++) m = fmaxf(m, fmaxf(f[i].x, f[i].y));
#pragma unroll
    for (int o = 16; o; o >>= 1) m = fmaxf(m, __shfl_xor_sync(0xffffffffu, m, o));
    __shared__ float smax[4], ssum[4];
    if (lane == 0) smax[warp] = m;
    __syncthreads();
    m = fmaxf(fmaxf(smax[0], smax[1]), fmaxf(smax[2], smax[3]));

    float e[8];
    float s = 0.f;
#pragma unroll
    for (int i = 0; i < 4; i++) {
        e[2 * i]     = __expf(f[i].x - m);
        e[2 * i + 1] = __expf(f[i].y - m);
        s += e[2 * i] + e[2 * i + 1];
    }
#pragma unroll
    for (int o = 16; o; o >>= 1) s += __shfl_xor_sync(0xffffffffu, s, o);
    if (lane == 0) ssum[warp] = s;
    __syncthreads();
    float inv = 1.0f / (ssum[0] + ssum[1] + ssum[2] + ssum[3]);

    uint4 w;
    *(__half2*)&w.x = __floats2half2_rn(e[0] * inv, e[1] * inv);
    *(__half2*)&w.y = __floats2half2_rn(e[2] * inv, e[3] * inv);
    *(__half2*)&w.z = __floats2half2_rn(e[4] * inv, e[5] * inv);
    *(__half2*)&w.w = __floats2half2_rn(e[6] * inv, e[7] * inv);
    p[tid] = w;
}

// ---------------------------------------------------------------------------
extern "C" void kernel_launch(void* const* d_in, const int* in_sizes, int n_in,
                              void* d_out, int out_size) {
    (void)in_sizes; (void)n_in; (void)out_size;
    const float* inputs = (const float*)d_in[0];
    const float* gamma  = (const float*)d_in[1];
    const float* beta   = (const float*)d_in[2];
    const float* Wqkv   = (const float*)d_in[3];
    const float* bqkv   = (const float*)d_in[4];
    const float* Wout   = (const float*)d_in[5];
    const float* bout   = (const float*)d_in[6];
    float* out = (float*)d_out;

    const int smNT = 3 * (128 * 128 + 128 * 128);        // 98304
    const int smNN = 3 * (128 * 128 + 64 * 136 * 2);     // 101376
    cudaFuncSetAttribute(gemm_mma<0>, cudaFuncAttributeMaxDynamicSharedMemorySize, smNT);
    cudaFuncSetAttribute(gemm_mma<1>, cudaFuncAttributeMaxDynamicSharedMemorySize, smNT);
    cudaFuncSetAttribute(gemm_mma<2>, cudaFuncAttributeMaxDynamicSharedMemorySize, smNN);
    cudaFuncSetAttribute(gemm_mma<3>, cudaFuncAttributeMaxDynamicSharedMemorySize, smNN);

    conv_wqkv<<<(NQKV * C + 255) / 256, 256>>>(Wqkv, bqkv);
    f2h_wout<<<(C * C + 255) / 256, 256>>>(Wout);
    groupnorm_kernel<<<BNUM * G, 256>>>(inputs, gamma, beta);

    gemm_mma<0><<<NPERS, 128, smNT>>>(nullptr, nullptr, nullptr);
    gemm_mma<1><<<NPERS, 128, smNT>>>(nullptr, nullptr, nullptr);
    softmax_h<<<BNUM * HW, 128>>>();
    gemm_mma<2><<<NPERS, 128, smNN>>>(nullptr, nullptr, nullptr);
    gemm_mma<3><<<NPERS, 128, smNN>>>(bout, inputs, out);
}